// round 9
// baseline (speedup 1.0000x reference)
#include <cuda_runtime.h>
#include <cuda_bf16.h>
#include <cstdint>

// Problem constants (fixed by the dataset): input [B, C, T] fp32
#define B_DIM 16
#define C_DIM 256
#define T_DIM 16000
#define EPS 1e-8f

#define TPB 256
#define T_PER_BLK 1024                 // 256 threads x 4 t (float4)
#define NCHUNK ((T_DIM + T_PER_BLK - 1) / T_PER_BLK)   // 16
#define C_SPLIT 4                      // K1: channel splits
#define CPS (C_DIM / C_SPLIT)          // 64 channels per split

#define K3_CSPLIT 4                    // K3: channel slices per (b, chunk)
#define K3_CPS (C_DIM / K3_CSPLIT)     // 64 channels per block

// scratch (device globals; allocation is forbidden)
__device__ float2 g_part [C_SPLIT * B_DIM * T_DIM]; // partial (sum,sumsq)  8 MB
__device__ float2 g_stats[B_DIM * T_DIM];           // (mean, inv_std)      2 MB

// ---------------- K1: partial channel reduction (pure streaming) ----------------
__global__ __launch_bounds__(TPB) void colsum_kernel(const float* __restrict__ x)
{
    const int cs = blockIdx.y;          // channel split 0..3
    const int b  = blockIdx.z;
    const int t4 = blockIdx.x * T_PER_BLK + threadIdx.x * 4;
    if (t4 >= T_DIM) return;            // 640 % 4 == 0: thread fully valid or not

    const float* px = x + ((size_t)b * C_DIM + cs * CPS) * T_DIM + t4;

    float4 s = make_float4(0.f, 0.f, 0.f, 0.f);
    float4 p = make_float4(0.f, 0.f, 0.f, 0.f);
    #pragma unroll 8
    for (int c = 0; c < CPS; c++) {
        const float4 v = __ldcs((const float4*)(px + (size_t)c * T_DIM));
        s.x += v.x; s.y += v.y; s.z += v.z; s.w += v.w;
        p.x = fmaf(v.x, v.x, p.x); p.y = fmaf(v.y, v.y, p.y);
        p.z = fmaf(v.z, v.z, p.z); p.w = fmaf(v.w, v.w, p.w);
    }

    float2* dst = g_part + ((size_t)cs * B_DIM + b) * T_DIM + t4;
    ((float4*)dst)[0] = make_float4(s.x, p.x, s.y, p.y);
    ((float4*)dst)[1] = make_float4(s.z, p.z, s.w, p.w);
}

// ---------------- K2: combine partials + per-batch scan -> (mean, inv_std) ----------------
#define SCAN_TPB 1024
#define EPT 16                                        // 1024*16 >= 16000

__global__ __launch_bounds__(SCAN_TPB) void scan_kernel()
{
    __shared__ float swS[32], swP[32];

    const int b    = blockIdx.x;
    const int tid  = threadIdx.x;
    const int lane = tid & 31;
    const int wid  = tid >> 5;
    const int start = tid * EPT;

    // read 4 partial streams directly (8 MB total, high MLP), combine + local scan
    float vs[EPT], vp[EPT];
    #pragma unroll
    for (int j = 0; j < EPT; j++) {
        const int i = start + j;
        float S = 0.f, P = 0.f;
        if (i < T_DIM) {
            #pragma unroll
            for (int cs = 0; cs < C_SPLIT; cs++) {
                const float2 v = g_part[((size_t)cs * B_DIM + b) * T_DIM + i];
                S += v.x; P += v.y;
            }
        }
        vs[j] = S; vp[j] = P;
    }
    #pragma unroll
    for (int j = 1; j < EPT; j++) { vs[j] += vs[j - 1]; vp[j] += vp[j - 1]; }

    // block-exclusive prefix of thread totals (warp shuffle, two levels)
    float tS = vs[EPT - 1], tP = vp[EPT - 1];
    float iS = tS, iP = tP;
    #pragma unroll
    for (int off = 1; off < 32; off <<= 1) {
        float nS = __shfl_up_sync(0xffffffffu, iS, off);
        float nP = __shfl_up_sync(0xffffffffu, iP, off);
        if (lane >= off) { iS += nS; iP += nP; }
    }
    if (lane == 31) { swS[wid] = iS; swP[wid] = iP; }
    __syncthreads();
    if (wid == 0) {
        float wS = swS[lane], wP = swP[lane];
        #pragma unroll
        for (int off = 1; off < 32; off <<= 1) {
            float nS = __shfl_up_sync(0xffffffffu, wS, off);
            float nP = __shfl_up_sync(0xffffffffu, wP, off);
            if (lane >= off) { wS += nS; wP += nP; }
        }
        swS[lane] = wS - swS[lane];               // exclusive warp offset
        swP[lane] = wP - swP[lane];
    }
    __syncthreads();
    const float excS = swS[wid] + (iS - tS);
    const float excP = swP[wid] + (iP - tP);

    const size_t base = (size_t)b * T_DIM;
    #pragma unroll
    for (int j = 0; j < EPT; j++) {
        const int i = start + j;
        if (i < T_DIM) {
            const float cumS = excS + vs[j];
            const float cumP = excP + vp[j];
            const float cnt  = (float)(i + 1) * (float)C_DIM;
            const float mean = cumS / cnt;
            const float inv  = rsqrtf(cumP / cnt - mean * mean + EPS);
            g_stats[base + i] = make_float2(mean, inv);
        }
    }
}

// ---------------- K3: normalize; stats in registers, channels looped ----------------
__global__ __launch_bounds__(TPB) void norm_kernel(
    const float* __restrict__ x,
    const float* __restrict__ gain,
    const float* __restrict__ bias,
    float* __restrict__ out)
{
    __shared__ float s_gain[K3_CPS];
    __shared__ float s_bias[K3_CPS];

    const int cs = blockIdx.y;          // channel slice 0..3
    const int b  = blockIdx.z;
    const int c0 = cs * K3_CPS;

    if (threadIdx.x < K3_CPS) {
        s_gain[threadIdx.x] = gain[c0 + threadIdx.x];
        s_bias[threadIdx.x] = bias[c0 + threadIdx.x];
    }
    __syncthreads();

    const int t4 = blockIdx.x * T_PER_BLK + threadIdx.x * 4;
    if (t4 >= T_DIM) return;

    // per-thread stats: loaded ONCE, reused across all 64 channels
    const float4* sp = (const float4*)(g_stats + (size_t)b * T_DIM + t4);
    const float4 s01 = sp[0];           // {mean0, inv0, mean1, inv1}
    const float4 s23 = sp[1];

    const size_t base = ((size_t)b * C_DIM + c0) * T_DIM + t4;
    const float* px = x   + base;
    float*       po = out + base;

    #pragma unroll 8
    for (int c = 0; c < K3_CPS; c++) {
        const float g  = s_gain[c];
        const float bi = s_bias[c];
        const float4 v = __ldcs((const float4*)(px + (size_t)c * T_DIM));
        float4 o;
        o.x = fmaf((v.x - s01.x) * s01.y, g, bi);
        o.y = fmaf((v.y - s01.z) * s01.w, g, bi);
        o.z = fmaf((v.z - s23.x) * s23.y, g, bi);
        o.w = fmaf((v.w - s23.z) * s23.w, g, bi);
        __stcs((float4*)(po + (size_t)c * T_DIM), o);
    }
}

extern "C" void kernel_launch(void* const* d_in, const int* in_sizes, int n_in,
                              void* d_out, int out_size)
{
    const float* x    = (const float*)d_in[0];
    const float* gain = (const float*)d_in[1];
    const float* bias = (const float*)d_in[2];
    float* out = (float*)d_out;

    colsum_kernel<<<dim3(NCHUNK, C_SPLIT, B_DIM), TPB>>>(x);
    scan_kernel  <<<B_DIM, SCAN_TPB>>>();
    norm_kernel  <<<dim3(NCHUNK, K3_CSPLIT, B_DIM), TPB>>>(x, gain, bias, out);
}

// round 10
// speedup vs baseline: 1.2165x; 1.2165x over previous
#include <cuda_runtime.h>
#include <cuda_bf16.h>
#include <cstdint>

// Problem constants (fixed by the dataset): input [B, C, T] fp32
#define B_DIM 16
#define C_DIM 256
#define T_DIM 16000
#define EPS 1e-8f

#define TPB 256
#define T_PER_BLK 1024                 // 256 threads x 4 t (float4)
#define NCHUNK ((T_DIM + T_PER_BLK - 1) / T_PER_BLK)   // 16
#define C_SPLIT 4                      // K1: channel splits
#define CPS (C_DIM / C_SPLIT)          // 64 channels per split

#define K3_CSPLIT 4                    // K3: channel slices per (b, chunk)
#define K3_CPS (C_DIM / K3_CSPLIT)     // 64 channels per block

// scratch (device globals; allocation is forbidden)
__device__ float2 g_part [C_SPLIT * B_DIM * T_DIM]; // partial (sum,sumsq)  8 MB
__device__ float2 g_stats[B_DIM * T_DIM];           // (mean, inv_std)      2 MB

// ---------------- K1: partial channel reduction (pure streaming) ----------------
__global__ __launch_bounds__(TPB) void colsum_kernel(const float* __restrict__ x)
{
    const int cs = blockIdx.y;          // channel split 0..3
    const int b  = blockIdx.z;
    const int t4 = blockIdx.x * T_PER_BLK + threadIdx.x * 4;
    if (t4 >= T_DIM) return;            // 640 % 4 == 0: thread fully valid or not

    const float* px = x + ((size_t)b * C_DIM + cs * CPS) * T_DIM + t4;

    float4 s = make_float4(0.f, 0.f, 0.f, 0.f);
    float4 p = make_float4(0.f, 0.f, 0.f, 0.f);
    #pragma unroll 8
    for (int c = 0; c < CPS; c++) {
        const float4 v = __ldcs((const float4*)(px + (size_t)c * T_DIM));
        s.x += v.x; s.y += v.y; s.z += v.z; s.w += v.w;
        p.x = fmaf(v.x, v.x, p.x); p.y = fmaf(v.y, v.y, p.y);
        p.z = fmaf(v.z, v.z, p.z); p.w = fmaf(v.w, v.w, p.w);
    }

    float2* dst = g_part + ((size_t)cs * B_DIM + b) * T_DIM + t4;
    ((float4*)dst)[0] = make_float4(s.x, p.x, s.y, p.y);
    ((float4*)dst)[1] = make_float4(s.z, p.z, s.w, p.w);
}

// ---------------- K2: combine (coalesced) + scan via smem staging ----------------
#define SCAN_TPB 1024
#define EPT 16                                        // 1000 threads x 16 = 16000
#define SKEW(i) ((i) + ((i) >> 4))                    // kill bank conflicts of blocked access
#define SM_ELEMS (T_DIM + T_DIM / 16)                 // 17000 float2 = 136 KB

__global__ __launch_bounds__(SCAN_TPB) void scan_kernel()
{
    extern __shared__ float2 sm[];                    // skewed (S, P) per timestep
    __shared__ float swS[32], swP[32];

    const int b    = blockIdx.x;
    const int tid  = threadIdx.x;
    const int lane = tid & 31;
    const int wid  = tid >> 5;

    // ---- Phase A: coalesced combine of 4 partial streams into smem ----
    const float4* p4 = (const float4*)g_part;         // {S0,P0,S1,P1} per entry
    const size_t strm = (size_t)B_DIM * T_DIM / 2;    // float4s per cs stream
    const size_t b4   = (size_t)b * (T_DIM / 2);
    for (int i2 = tid; i2 < T_DIM / 2; i2 += SCAN_TPB) {
        float4 a0 = p4[b4 + i2];
        const float4 a1 = p4[strm + b4 + i2];
        const float4 a2 = p4[2 * strm + b4 + i2];
        const float4 a3 = p4[3 * strm + b4 + i2];
        a0.x += a1.x + a2.x + a3.x;  a0.y += a1.y + a2.y + a3.y;
        a0.z += a1.z + a2.z + a3.z;  a0.w += a1.w + a2.w + a3.w;
        const int i = i2 * 2;
        sm[SKEW(i)]     = make_float2(a0.x, a0.y);
        sm[SKEW(i + 1)] = make_float2(a0.z, a0.w);
    }
    __syncthreads();

    // ---- Phase B: blocked local scan from smem ----
    const int start = tid * EPT;
    float vs[EPT], vp[EPT];
    #pragma unroll
    for (int j = 0; j < EPT; j++) {
        const int i = start + j;
        const float2 v = (i < T_DIM) ? sm[SKEW(i)] : make_float2(0.f, 0.f);
        vs[j] = v.x; vp[j] = v.y;
    }
    #pragma unroll
    for (int j = 1; j < EPT; j++) { vs[j] += vs[j - 1]; vp[j] += vp[j - 1]; }

    float tS = vs[EPT - 1], tP = vp[EPT - 1];
    float iS = tS, iP = tP;
    #pragma unroll
    for (int off = 1; off < 32; off <<= 1) {
        float nS = __shfl_up_sync(0xffffffffu, iS, off);
        float nP = __shfl_up_sync(0xffffffffu, iP, off);
        if (lane >= off) { iS += nS; iP += nP; }
    }
    if (lane == 31) { swS[wid] = iS; swP[wid] = iP; }
    __syncthreads();
    if (wid == 0) {
        float wS = swS[lane], wP = swP[lane];
        #pragma unroll
        for (int off = 1; off < 32; off <<= 1) {
            float nS = __shfl_up_sync(0xffffffffu, wS, off);
            float nP = __shfl_up_sync(0xffffffffu, wP, off);
            if (lane >= off) { wS += nS; wP += nP; }
        }
        swS[lane] = wS - swS[lane];               // exclusive warp offset
        swP[lane] = wP - swP[lane];
    }
    __syncthreads();
    const float excS = swS[wid] + (iS - tS);
    const float excP = swP[wid] + (iP - tP);

    // write (mean, inv) back into smem (same skewed slots)
    #pragma unroll
    for (int j = 0; j < EPT; j++) {
        const int i = start + j;
        if (i < T_DIM) {
            const float cumS = excS + vs[j];
            const float cumP = excP + vp[j];
            const float cnt  = (float)(i + 1) * (float)C_DIM;
            const float mean = cumS / cnt;
            const float inv  = rsqrtf(cumP / cnt - mean * mean + EPS);
            sm[SKEW(i)] = make_float2(mean, inv);
        }
    }
    __syncthreads();

    // ---- Phase C: coalesced float4 writeback of stats ----
    float4* st4 = (float4*)g_stats;
    for (int i2 = tid; i2 < T_DIM / 2; i2 += SCAN_TPB) {
        const int i = i2 * 2;
        const float2 a = sm[SKEW(i)];
        const float2 c = sm[SKEW(i + 1)];
        st4[b4 + i2] = make_float4(a.x, a.y, c.x, c.y);
    }
}

// ---------------- K3: normalize; stats in registers, channels looped ----------------
__global__ __launch_bounds__(TPB) void norm_kernel(
    const float* __restrict__ x,
    const float* __restrict__ gain,
    const float* __restrict__ bias,
    float* __restrict__ out)
{
    __shared__ float s_gain[K3_CPS];
    __shared__ float s_bias[K3_CPS];

    const int cs = blockIdx.y;          // channel slice 0..3
    const int b  = blockIdx.z;
    const int c0 = cs * K3_CPS;

    if (threadIdx.x < K3_CPS) {
        s_gain[threadIdx.x] = gain[c0 + threadIdx.x];
        s_bias[threadIdx.x] = bias[c0 + threadIdx.x];
    }
    __syncthreads();

    const int t4 = blockIdx.x * T_PER_BLK + threadIdx.x * 4;
    if (t4 >= T_DIM) return;

    // per-thread stats: loaded ONCE, reused across all 64 channels
    const float4* sp = (const float4*)(g_stats + (size_t)b * T_DIM + t4);
    const float4 s01 = sp[0];           // {mean0, inv0, mean1, inv1}
    const float4 s23 = sp[1];

    const size_t base = ((size_t)b * C_DIM + c0) * T_DIM + t4;
    const float* px = x   + base;
    float*       po = out + base;

    #pragma unroll 8
    for (int c = 0; c < K3_CPS; c++) {
        const float g  = s_gain[c];
        const float bi = s_bias[c];
        const float4 v = __ldcs((const float4*)(px + (size_t)c * T_DIM));
        float4 o;
        o.x = fmaf((v.x - s01.x) * s01.y, g, bi);
        o.y = fmaf((v.y - s01.z) * s01.w, g, bi);
        o.z = fmaf((v.z - s23.x) * s23.y, g, bi);
        o.w = fmaf((v.w - s23.z) * s23.w, g, bi);
        __stcs((float4*)(po + (size_t)c * T_DIM), o);
    }
}

extern "C" void kernel_launch(void* const* d_in, const int* in_sizes, int n_in,
                              void* d_out, int out_size)
{
    const float* x    = (const float*)d_in[0];
    const float* gain = (const float*)d_in[1];
    const float* bias = (const float*)d_in[2];
    float* out = (float*)d_out;

    static int smem_set = 0;
    if (!smem_set) {
        cudaFuncSetAttribute(scan_kernel, cudaFuncAttributeMaxDynamicSharedMemorySize,
                             SM_ELEMS * sizeof(float2));
        smem_set = 1;
    }

    colsum_kernel<<<dim3(NCHUNK, C_SPLIT, B_DIM), TPB>>>(x);
    scan_kernel  <<<B_DIM, SCAN_TPB, SM_ELEMS * sizeof(float2)>>>();
    norm_kernel  <<<dim3(NCHUNK, K3_CSPLIT, B_DIM), TPB>>>(x, gain, bias, out);
}

// round 11
// speedup vs baseline: 1.2249x; 1.0069x over previous
#include <cuda_runtime.h>
#include <cuda_bf16.h>
#include <cstdint>

// Problem constants (fixed by the dataset): input [B, C, T] fp32
#define B_DIM 16
#define C_DIM 256
#define T_DIM 16000
#define EPS 1e-8f

#define TPB 256
#define T_PER_BLK 1024                 // 256 threads x 4 t (float4)
#define NCHUNK ((T_DIM + T_PER_BLK - 1) / T_PER_BLK)   // 16
#define C_SPLIT 4                      // K1: channel splits
#define CPS (C_DIM / C_SPLIT)          // 64 channels per split

#define K3_CSPLIT 4                    // K3: channel slices per (b, chunk)
#define K3_CPS (C_DIM / K3_CSPLIT)     // 64 channels per block

// scratch (device globals; allocation is forbidden)
__device__ float2 g_part [C_SPLIT * B_DIM * T_DIM]; // partial (sum,sumsq)  8 MB
__device__ float2 g_stats[B_DIM * T_DIM];           // (mean, inv_std)      2 MB

// ---------------- K1: partial channel reduction (pure streaming) ----------------
__global__ __launch_bounds__(TPB) void colsum_kernel(const float* __restrict__ x)
{
    const int cs = blockIdx.y;          // channel split 0..3
    const int b  = blockIdx.z;
    const int t4 = blockIdx.x * T_PER_BLK + threadIdx.x * 4;
    if (t4 >= T_DIM) return;            // 640 % 4 == 0: thread fully valid or not

    const float* px = x + ((size_t)b * C_DIM + cs * CPS) * T_DIM + t4;

    float4 s = make_float4(0.f, 0.f, 0.f, 0.f);
    float4 p = make_float4(0.f, 0.f, 0.f, 0.f);
    #pragma unroll 8
    for (int c = 0; c < CPS; c++) {
        const float4 v = __ldcs((const float4*)(px + (size_t)c * T_DIM));
        s.x += v.x; s.y += v.y; s.z += v.z; s.w += v.w;
        p.x = fmaf(v.x, v.x, p.x); p.y = fmaf(v.y, v.y, p.y);
        p.z = fmaf(v.z, v.z, p.z); p.w = fmaf(v.w, v.w, p.w);
    }

    float2* dst = g_part + ((size_t)cs * B_DIM + b) * T_DIM + t4;
    ((float4*)dst)[0] = make_float4(s.x, p.x, s.y, p.y);
    ((float4*)dst)[1] = make_float4(s.z, p.z, s.w, p.w);
}

// ---------------- K2: combine (coalesced) + scan via smem staging ----------------
#define SCAN_TPB 1024
#define EPT 16                                        // 1000 threads x 16 = 16000
#define SKEW(i) ((i) + ((i) >> 4))                    // kill bank conflicts of blocked access
#define SM_ELEMS (T_DIM + T_DIM / 16)                 // 17000 float2 = 136 KB

__global__ __launch_bounds__(SCAN_TPB) void scan_kernel()
{
    extern __shared__ float2 sm[];                    // skewed (S, P) per timestep
    __shared__ float swS[32], swP[32];

    const int b    = blockIdx.x;
    const int tid  = threadIdx.x;
    const int lane = tid & 31;
    const int wid  = tid >> 5;

    const float4* p4 = (const float4*)g_part;         // {S0,P0,S1,P1} per entry
    const size_t strm = (size_t)B_DIM * T_DIM / 2;    // float4s per cs stream
    const size_t b4   = (size_t)b * (T_DIM / 2);

#if __CUDA_ARCH__ >= 900
    // PDL: wait for colsum_kernel's memory to be visible (launch/prologue overlapped)
    cudaGridDependencySynchronize();
#endif

    // ---- Phase A: coalesced combine of 4 partial streams into smem ----
    for (int i2 = tid; i2 < T_DIM / 2; i2 += SCAN_TPB) {
        float4 a0 = p4[b4 + i2];
        const float4 a1 = p4[strm + b4 + i2];
        const float4 a2 = p4[2 * strm + b4 + i2];
        const float4 a3 = p4[3 * strm + b4 + i2];
        a0.x += a1.x + a2.x + a3.x;  a0.y += a1.y + a2.y + a3.y;
        a0.z += a1.z + a2.z + a3.z;  a0.w += a1.w + a2.w + a3.w;
        const int i = i2 * 2;
        sm[SKEW(i)]     = make_float2(a0.x, a0.y);
        sm[SKEW(i + 1)] = make_float2(a0.z, a0.w);
    }
    __syncthreads();

    // ---- Phase B: blocked local scan from smem ----
    const int start = tid * EPT;
    float vs[EPT], vp[EPT];
    #pragma unroll
    for (int j = 0; j < EPT; j++) {
        const int i = start + j;
        const float2 v = (i < T_DIM) ? sm[SKEW(i)] : make_float2(0.f, 0.f);
        vs[j] = v.x; vp[j] = v.y;
    }
    #pragma unroll
    for (int j = 1; j < EPT; j++) { vs[j] += vs[j - 1]; vp[j] += vp[j - 1]; }

    float tS = vs[EPT - 1], tP = vp[EPT - 1];
    float iS = tS, iP = tP;
    #pragma unroll
    for (int off = 1; off < 32; off <<= 1) {
        float nS = __shfl_up_sync(0xffffffffu, iS, off);
        float nP = __shfl_up_sync(0xffffffffu, iP, off);
        if (lane >= off) { iS += nS; iP += nP; }
    }
    if (lane == 31) { swS[wid] = iS; swP[wid] = iP; }
    __syncthreads();
    if (wid == 0) {
        float wS = swS[lane], wP = swP[lane];
        #pragma unroll
        for (int off = 1; off < 32; off <<= 1) {
            float nS = __shfl_up_sync(0xffffffffu, wS, off);
            float nP = __shfl_up_sync(0xffffffffu, wP, off);
            if (lane >= off) { wS += nS; wP += nP; }
        }
        swS[lane] = wS - swS[lane];               // exclusive warp offset
        swP[lane] = wP - swP[lane];
    }
    __syncthreads();
    const float excS = swS[wid] + (iS - tS);
    const float excP = swP[wid] + (iP - tP);

    // write (mean, inv) back into smem (same skewed slots)
    #pragma unroll
    for (int j = 0; j < EPT; j++) {
        const int i = start + j;
        if (i < T_DIM) {
            const float cumS = excS + vs[j];
            const float cumP = excP + vp[j];
            const float cnt  = (float)(i + 1) * (float)C_DIM;
            const float mean = cumS / cnt;
            const float inv  = rsqrtf(cumP / cnt - mean * mean + EPS);
            sm[SKEW(i)] = make_float2(mean, inv);
        }
    }
    __syncthreads();

    // ---- Phase C: coalesced float4 writeback of stats ----
    float4* st4 = (float4*)g_stats;
    for (int i2 = tid; i2 < T_DIM / 2; i2 += SCAN_TPB) {
        const int i = i2 * 2;
        const float2 a = sm[SKEW(i)];
        const float2 c = sm[SKEW(i + 1)];
        st4[b4 + i2] = make_float4(a.x, a.y, c.x, c.y);
    }
}

// ---------------- K3: normalize; stats in registers, channels looped ----------------
__global__ __launch_bounds__(TPB) void norm_kernel(
    const float* __restrict__ x,
    const float* __restrict__ gain,
    const float* __restrict__ bias,
    float* __restrict__ out)
{
    __shared__ float s_gain[K3_CPS];
    __shared__ float s_bias[K3_CPS];

    const int cs = blockIdx.y;          // channel slice 0..3
    const int b  = blockIdx.z;
    const int c0 = cs * K3_CPS;

    // Everything independent of the scan runs BEFORE the dependency sync.
    if (threadIdx.x < K3_CPS) {
        s_gain[threadIdx.x] = gain[c0 + threadIdx.x];
        s_bias[threadIdx.x] = bias[c0 + threadIdx.x];
    }
    __syncthreads();

    const int t4 = blockIdx.x * T_PER_BLK + threadIdx.x * 4;
    if (t4 >= T_DIM) return;

    const size_t base = ((size_t)b * C_DIM + c0) * T_DIM + t4;
    const float* px = x   + base;
    float*       po = out + base;

#if __CUDA_ARCH__ >= 900
    // PDL: wait for scan_kernel's stats to be visible
    cudaGridDependencySynchronize();
#endif

    // per-thread stats: loaded ONCE, reused across all 64 channels
    const float4* sp = (const float4*)(g_stats + (size_t)b * T_DIM + t4);
    const float4 s01 = sp[0];           // {mean0, inv0, mean1, inv1}
    const float4 s23 = sp[1];

    #pragma unroll 8
    for (int c = 0; c < K3_CPS; c++) {
        const float g  = s_gain[c];
        const float bi = s_bias[c];
        const float4 v = __ldcs((const float4*)(px + (size_t)c * T_DIM));
        float4 o;
        o.x = fmaf((v.x - s01.x) * s01.y, g, bi);
        o.y = fmaf((v.y - s01.z) * s01.w, g, bi);
        o.z = fmaf((v.z - s23.x) * s23.y, g, bi);
        o.w = fmaf((v.w - s23.z) * s23.w, g, bi);
        __stcs((float4*)(po + (size_t)c * T_DIM), o);
    }
}

extern "C" void kernel_launch(void* const* d_in, const int* in_sizes, int n_in,
                              void* d_out, int out_size)
{
    const float* x    = (const float*)d_in[0];
    const float* gain = (const float*)d_in[1];
    const float* bias = (const float*)d_in[2];
    float* out = (float*)d_out;

    static int smem_set = 0;
    if (!smem_set) {
        cudaFuncSetAttribute(scan_kernel, cudaFuncAttributeMaxDynamicSharedMemorySize,
                             SM_ELEMS * sizeof(float2));
        smem_set = 1;
    }

    // K1: normal launch
    colsum_kernel<<<dim3(NCHUNK, C_SPLIT, B_DIM), TPB>>>(x);

    // K2: PDL launch — scheduled while K1 drains; syncs on K1's memory in-kernel
    {
        cudaLaunchAttribute attr[1];
        attr[0].id = cudaLaunchAttributeProgrammaticStreamSerialization;
        attr[0].val.programmaticStreamSerializationAllowed = 1;
        cudaLaunchConfig_t cfg = {};
        cfg.gridDim = dim3(B_DIM);
        cfg.blockDim = dim3(SCAN_TPB);
        cfg.dynamicSmemBytes = SM_ELEMS * sizeof(float2);
        cfg.stream = 0;
        cfg.attrs = attr;
        cfg.numAttrs = 1;
        cudaLaunchKernelEx(&cfg, scan_kernel);
    }

    // K3: PDL launch — prologue (gain/bias staging) overlaps scan's tail
    {
        cudaLaunchAttribute attr[1];
        attr[0].id = cudaLaunchAttributeProgrammaticStreamSerialization;
        attr[0].val.programmaticStreamSerializationAllowed = 1;
        cudaLaunchConfig_t cfg = {};
        cfg.gridDim = dim3(NCHUNK, K3_CSPLIT, B_DIM);
        cfg.blockDim = dim3(TPB);
        cfg.stream = 0;
        cfg.attrs = attr;
        cfg.numAttrs = 1;
        cudaLaunchKernelEx(&cfg, norm_kernel, x, gain, bias, out);
    }
}

// round 13
// speedup vs baseline: 1.2676x; 1.0349x over previous
#include <cuda_runtime.h>
#include <cuda_bf16.h>
#include <cstdint>

// Problem constants (fixed by the dataset): input [B, C, T] fp32
#define B_DIM 16
#define C_DIM 256
#define T_DIM 16000
#define EPS 1e-8f

#define TPB 256
#define T_PER_BLK 1024                 // 256 threads x 4 t (float4)
#define NCHUNK ((T_DIM + T_PER_BLK - 1) / T_PER_BLK)   // 16
#define C_SPLIT 4                      // K1: channel splits
#define CPS (C_DIM / C_SPLIT)          // 64 channels per split

#define K3_CSPLIT 4                    // K3: channel slices per (b, chunk)
#define K3_CPS (C_DIM / K3_CSPLIT)     // 64 channels per block

#define OCT 8                          // scan octants per batch
#define OCT_T (T_DIM / OCT)            // 2000 timesteps per octant

// scratch (device globals; allocation is forbidden)
__device__ float2 g_part[C_SPLIT * B_DIM * T_DIM]; // partial (sum,sumsq)  8 MB
__device__ float2 g_scan[B_DIM * T_DIM];           // octant-local inclusive (S,P) 2 MB
__device__ float2 g_agg [B_DIM * OCT];             // octant aggregates
__device__ float2 g_off [B_DIM * OCT];             // octant exclusive offsets
__device__ int    g_cnt;                           // last-block counter (self-resetting)

// ---------------- K1: partial channel reduction (pure streaming) ----------------
__global__ __launch_bounds__(TPB) void colsum_kernel(const float* __restrict__ x)
{
    const int cs = blockIdx.y;          // channel split 0..3
    const int b  = blockIdx.z;
    const int t4 = blockIdx.x * T_PER_BLK + threadIdx.x * 4;
    if (t4 >= T_DIM) return;            // 640 % 4 == 0: thread fully valid or not

    const float* px = x + ((size_t)b * C_DIM + cs * CPS) * T_DIM + t4;

    float4 s = make_float4(0.f, 0.f, 0.f, 0.f);
    float4 p = make_float4(0.f, 0.f, 0.f, 0.f);
    #pragma unroll 8
    for (int c = 0; c < CPS; c++) {
        const float4 v = __ldcs((const float4*)(px + (size_t)c * T_DIM));
        s.x += v.x; s.y += v.y; s.z += v.z; s.w += v.w;
        p.x = fmaf(v.x, v.x, p.x); p.y = fmaf(v.y, v.y, p.y);
        p.z = fmaf(v.z, v.z, p.z); p.w = fmaf(v.w, v.w, p.w);
    }

    float2* dst = g_part + ((size_t)cs * B_DIM + b) * T_DIM + t4;
    ((float4*)dst)[0] = make_float4(s.x, p.x, s.y, p.y);
    ((float4*)dst)[1] = make_float4(s.z, p.z, s.w, p.w);
}

// ------- K2: octant-parallel combine+scan (128 blocks) + fused 2nd level -------
#define SCAN_TPB 1024

__global__ __launch_bounds__(SCAN_TPB) void scan2_kernel()
{
    __shared__ float2 sm[OCT_T];                     // 16 KB local (S,P)
    __shared__ float  swS[32], swP[32];
    __shared__ int    s_last;

    const int o    = blockIdx.x;                     // octant 0..7
    const int b    = blockIdx.y;                     // batch
    const int tid  = threadIdx.x;
    const int lane = tid & 31;
    const int wid  = tid >> 5;

    const float4* p4   = (const float4*)g_part;      // {S0,P0,S1,P1} per pair
    const size_t  strm = (size_t)B_DIM * T_DIM / 2;  // float4s per cs stream
    const size_t  base4 = (size_t)b * (T_DIM / 2) + (size_t)o * (OCT_T / 2);

#if __CUDA_ARCH__ >= 900
    cudaGridDependencySynchronize();                 // wait for colsum_kernel
#endif

    // ---- Phase A: coalesced combine of 4 partial streams into smem ----
    if (tid < OCT_T / 2) {                           // 1000 active threads
        float4 a0 = p4[base4 + tid];
        const float4 a1 = p4[strm + base4 + tid];
        const float4 a2 = p4[2 * strm + base4 + tid];
        const float4 a3 = p4[3 * strm + base4 + tid];
        a0.x += a1.x + a2.x + a3.x;  a0.y += a1.y + a2.y + a3.y;
        a0.z += a1.z + a2.z + a3.z;  a0.w += a1.w + a2.w + a3.w;
        sm[2 * tid]     = make_float2(a0.x, a0.y);
        sm[2 * tid + 1] = make_float2(a0.z, a0.w);
    }
    __syncthreads();

    // ---- Phase B: local scan (EPT=2) ----
    const int  i0    = tid * 2;
    const bool valid = (i0 < OCT_T);
    float s0 = 0.f, p0 = 0.f, s1 = 0.f, p1 = 0.f;
    if (valid) {
        const float2 a = sm[i0];
        const float2 c = sm[i0 + 1];
        s0 = a.x; p0 = a.y;
        s1 = s0 + c.x; p1 = p0 + c.y;
    }
    float iS = s1, iP = p1;                          // thread-inclusive totals
    #pragma unroll
    for (int off = 1; off < 32; off <<= 1) {
        float nS = __shfl_up_sync(0xffffffffu, iS, off);
        float nP = __shfl_up_sync(0xffffffffu, iP, off);
        if (lane >= off) { iS += nS; iP += nP; }
    }
    if (lane == 31) { swS[wid] = iS; swP[wid] = iP; }
    __syncthreads();
    if (wid == 0) {
        float wS = swS[lane], wP = swP[lane];
        #pragma unroll
        for (int off = 1; off < 32; off <<= 1) {
            float nS = __shfl_up_sync(0xffffffffu, wS, off);
            float nP = __shfl_up_sync(0xffffffffu, wP, off);
            if (lane >= off) { wS += nS; wP += nP; }
        }
        swS[lane] = wS - swS[lane];                  // exclusive warp offsets
        swP[lane] = wP - swP[lane];
    }
    __syncthreads();
    const float excS = swS[wid] + (iS - s1);         // thread-exclusive prefix
    const float excP = swP[wid] + (iP - p1);

    // ---- write octant-local inclusive scan (coalesced float4) ----
    if (valid) {
        ((float4*)g_scan)[base4 + tid] =
            make_float4(excS + s0, excP + p0, excS + s1, excP + p1);
    }

    // ---- publish octant aggregate; last block does 2nd-level scan ----
    if (tid == OCT_T / 2 - 1) {                      // owns the octant total
        g_agg[b * OCT + o] = make_float2(excS + s1, excP + p1);
        __threadfence();
        const int old = atomicAdd(&g_cnt, 1);
        s_last = (old == gridDim.x * gridDim.y - 1) ? 1 : 0;
    }
    __syncthreads();

    if (s_last) {
        __threadfence();                             // acquire: see all g_agg
        if (tid < B_DIM) {
            float aS = 0.f, aP = 0.f;
            #pragma unroll
            for (int o2 = 0; o2 < OCT; o2++) {
                g_off[tid * OCT + o2] = make_float2(aS, aP);
                const float2 a = g_agg[tid * OCT + o2];
                aS += a.x; aP += a.y;
            }
        }
        __syncthreads();
        if (tid == 0) { __threadfence(); g_cnt = 0; }   // reset for next replay
    }
}

// ------- K3: normalize; local scan + octant offset -> stats computed inline -------
__global__ __launch_bounds__(TPB) void norm_kernel(
    const float* __restrict__ x,
    const float* __restrict__ gain,
    const float* __restrict__ bias,
    float* __restrict__ out)
{
    __shared__ float s_gain[K3_CPS];
    __shared__ float s_bias[K3_CPS];

    const int cs = blockIdx.y;          // channel slice 0..3
    const int b  = blockIdx.z;
    const int c0 = cs * K3_CPS;

    // independent of the scan: run before the dependency sync
    if (threadIdx.x < K3_CPS) {
        s_gain[threadIdx.x] = gain[c0 + threadIdx.x];
        s_bias[threadIdx.x] = bias[c0 + threadIdx.x];
    }
    __syncthreads();

    const int t4 = blockIdx.x * T_PER_BLK + threadIdx.x * 4;
    if (t4 >= T_DIM) return;

    const size_t base = ((size_t)b * C_DIM + c0) * T_DIM + t4;
    const float* px = x   + base;
    float*       po = out + base;

#if __CUDA_ARCH__ >= 900
    cudaGridDependencySynchronize();    // wait for scan2_kernel
#endif

    // octant offset (OCT_T multiple of 4 -> whole float4 in one octant)
    const float2 off = g_off[b * OCT + t4 / OCT_T];
    const float4* sp = (const float4*)(g_scan + (size_t)b * T_DIM + t4);
    const float4 l01 = sp[0];           // {S0,P0,S1,P1} local inclusive
    const float4 l23 = sp[1];

    float mean[4], inv[4];
    {
        const float S[4] = { l01.x, l01.z, l23.x, l23.z };
        const float P[4] = { l01.y, l01.w, l23.y, l23.w };
        #pragma unroll
        for (int j = 0; j < 4; j++) {
            const float cnt  = (float)(t4 + 1 + j) * (float)C_DIM;
            const float rc   = __fdividef(1.0f, cnt);
            const float m    = (off.x + S[j]) * rc;
            mean[j] = m;
            inv[j]  = rsqrtf((off.y + P[j]) * rc - m * m + EPS);
        }
    }

    #pragma unroll 8
    for (int c = 0; c < K3_CPS; c++) {
        const float g  = s_gain[c];
        const float bi = s_bias[c];
        const float4 v = __ldcs((const float4*)(px + (size_t)c * T_DIM));
        float4 o;
        o.x = fmaf((v.x - mean[0]) * inv[0], g, bi);
        o.y = fmaf((v.y - mean[1]) * inv[1], g, bi);
        o.z = fmaf((v.z - mean[2]) * inv[2], g, bi);
        o.w = fmaf((v.w - mean[3]) * inv[3], g, bi);
        __stcs((float4*)(po + (size_t)c * T_DIM), o);
    }
}

extern "C" void kernel_launch(void* const* d_in, const int* in_sizes, int n_in,
                              void* d_out, int out_size)
{
    const float* x    = (const float*)d_in[0];
    const float* gain = (const float*)d_in[1];
    const float* bias = (const float*)d_in[2];
    float* out = (float*)d_out;

    // K1: normal launch
    colsum_kernel<<<dim3(NCHUNK, C_SPLIT, B_DIM), TPB>>>(x);

    // K2: PDL launch (128 blocks; fused 2nd-level scan via last-block pattern)
    {
        cudaLaunchAttribute attr[1];
        attr[0].id = cudaLaunchAttributeProgrammaticStreamSerialization;
        attr[0].val.programmaticStreamSerializationAllowed = 1;
        cudaLaunchConfig_t cfg = {};
        cfg.gridDim = dim3(OCT, B_DIM);
        cfg.blockDim = dim3(SCAN_TPB);
        cfg.stream = 0;
        cfg.attrs = attr;
        cfg.numAttrs = 1;
        cudaLaunchKernelEx(&cfg, scan2_kernel);
    }

    // K3: PDL launch — prologue overlaps scan tail
    {
        cudaLaunchAttribute attr[1];
        attr[0].id = cudaLaunchAttributeProgrammaticStreamSerialization;
        attr[0].val.programmaticStreamSerializationAllowed = 1;
        cudaLaunchConfig_t cfg = {};
        cfg.gridDim = dim3(NCHUNK, K3_CSPLIT, B_DIM);
        cfg.blockDim = dim3(TPB);
        cfg.stream = 0;
        cfg.attrs = attr;
        cfg.numAttrs = 1;
        cudaLaunchKernelEx(&cfg, norm_kernel, x, gain, bias, out);
    }
}